// round 4
// baseline (speedup 1.0000x reference)
#include <cuda_runtime.h>
#include <cuda_bf16.h>

#define FEAT   24
#define NPIX   (FEAT*FEAT)        // 576
#define KANCH  9
#define NN     (NPIX*KANCH)       // 5184
#define MIDCH  24
#define CINCH  512
#define NWORD  81                 // 5184 / 64
#define NCH    41                 // chunks of 128 rows (last chunk = 64 rows)
#define IMGW   384.0f
#define IMGH   384.0f
#define NMS_T  0.7f
#define MINSZ  16.0f
#define KCHUNKS 16                // 512 / 32
#define CPART  32
#define NSLICE 8
#define SLICE  (NN / NSLICE)      // 648

typedef unsigned long long u64;

// ---------------- scratch (device globals; no allocation allowed) -------------
__device__ float g_hpart[KCHUNKS * MIDCH * NPIX];

__device__ float g_x0[NN], g_y0[NN], g_x1[NN], g_y1[NN];
__device__ float g_ws[NN], g_hs[NN], g_prob[NN];
__device__ unsigned g_valid[NN];
__device__ u64 g_keys[NN];
__device__ int g_rank[NN];

__device__ float g_bx0[NN], g_by0[NN], g_bx1[NN], g_by1[NN], g_barea[NN];
__device__ unsigned g_bvalid[NN];
__device__ int g_order[NN];

__device__ u64 g_mask[NN * NWORD];

// ---------------- 1. conv 3x3, 512->24, partial over K chunks -----------------
__global__ void conv_part_kernel(const float* __restrict__ x,
                                 const float* __restrict__ W) {
    const int y  = blockIdx.x;          // 0..23
    const int kc = blockIdx.y;          // 0..15
    const int c0 = kc * CPART;

    __shared__ float xs[CPART][3][26];
    __shared__ float ws[MIDCH][CPART][9];

    const int tid = threadIdx.x;        // 576 threads

    for (int idx = tid; idx < CPART * 3 * 26; idx += 576) {
        int c  = idx / 78;
        int r  = (idx % 78) / 26;
        int xx = idx % 26;
        int gy = y + r - 1;
        int gx = xx - 1;
        float v = 0.0f;
        if (gy >= 0 && gy < FEAT && gx >= 0 && gx < FEAT)
            v = x[(c0 + c) * NPIX + gy * FEAT + gx];
        xs[c][r][xx] = v;
    }
    for (int idx = tid; idx < MIDCH * CPART * 9; idx += 576) {
        int o = idx / (CPART * 9);
        int c = (idx % (CPART * 9)) / 9;
        int t = idx % 9;
        ws[o][c][t] = W[((o * CINCH) + c0 + c) * 9 + t];
    }
    __syncthreads();

    const int xc = tid % FEAT;
    const int o  = tid / FEAT;
    float acc = 0.0f;
    #pragma unroll 4
    for (int c = 0; c < CPART; c++) {
        float a0 = xs[c][0][xc], a1 = xs[c][0][xc+1], a2 = xs[c][0][xc+2];
        float b0 = xs[c][1][xc], b1 = xs[c][1][xc+1], b2 = xs[c][1][xc+2];
        float d0 = xs[c][2][xc], d1 = xs[c][2][xc+1], d2 = xs[c][2][xc+2];
        const float* w = ws[o][c];
        acc += a0*w[0] + a1*w[1] + a2*w[2]
             + b0*w[3] + b1*w[4] + b2*w[5]
             + d0*w[6] + d1*w[7] + d2*w[8];
    }
    g_hpart[kc * (MIDCH*NPIX) + o * NPIX + y * FEAT + xc] = acc;
}

// ---------------- 2. heads + decode (conv-reduce fused) -----------------------
__global__ __launch_bounds__(288) void decode_kernel(
        const float* __restrict__ Wc, const float* __restrict__ bc,
        const float* __restrict__ Wr, const float* __restrict__ br,
        const float* __restrict__ brpn,
        const float* __restrict__ anchors,
        float* __restrict__ out) {
    __shared__ float sh[32][MIDCH];
    __shared__ float sWc[2*KANCH*MIDCH];
    __shared__ float sWr[4*KANCH*MIDCH];
    __shared__ float sbc[2*KANCH];
    __shared__ float sbr[4*KANCH];

    const int tid = threadIdx.x;
    const int p0  = blockIdx.x * 32;

    for (int i = tid; i < 32 * MIDCH; i += 288) {
        int ch = i / 32, pp = i % 32;
        float s = 0.0f;
        #pragma unroll
        for (int kc = 0; kc < KCHUNKS; kc++)
            s += g_hpart[kc * (MIDCH*NPIX) + ch * NPIX + p0 + pp];
        sh[pp][ch] = fmaxf(s + brpn[ch], 0.0f);
    }
    for (int i = tid; i < 2*KANCH*MIDCH; i += 288) sWc[i] = Wc[i];
    for (int i = tid; i < 4*KANCH*MIDCH; i += 288) sWr[i] = Wr[i];
    if (tid < 2*KANCH) sbc[tid] = bc[tid];
    if (tid < 4*KANCH) sbr[tid] = br[tid];
    __syncthreads();

    const int lp = tid / KANCH;          // 0..31
    const int k  = tid % KANCH;
    const int n  = (p0 + lp) * KANCH + k;

    g_rank[n] = 0;                       // zero rank accumulator for this run

    float hv[MIDCH];
    #pragma unroll
    for (int o = 0; o < MIDCH; o++) hv[o] = sh[lp][o];

    float c0 = 0.0f, c1 = 0.0f;
    #pragma unroll
    for (int o = 0; o < MIDCH; o++) {
        c0 += hv[o] * sWc[(2*k)   * MIDCH + o];
        c1 += hv[o] * sWc[(2*k+1) * MIDCH + o];
    }
    c0 += sbc[2*k]; c1 += sbc[2*k+1];

    float tx = 0.0f, ty = 0.0f, tw = 0.0f, th = 0.0f;
    #pragma unroll
    for (int o = 0; o < MIDCH; o++) {
        float h = hv[o];
        tx += h * sWr[(4*k)   * MIDCH + o];
        ty += h * sWr[(4*k+1) * MIDCH + o];
        tw += h * sWr[(4*k+2) * MIDCH + o];
        th += h * sWr[(4*k+3) * MIDCH + o];
    }
    tx += sbr[4*k]; ty += sbr[4*k+1]; tw += sbr[4*k+2]; th += sbr[4*k+3];

    out[4*NN + 2*n]     = c0;
    out[4*NN + 2*n + 1] = c1;
    float prob = 1.0f / (1.0f + expf(c0 - c1));

    float ax = anchors[4*n],   ay = anchors[4*n+1];
    float aw = anchors[4*n+2], ah = anchors[4*n+3];

    float px = ax + aw * tx;
    float py = ay + ah * ty;
    float pw = aw * expf(tw);
    float ph = ah * expf(th);
    out[4*n]   = px; out[4*n+1] = py;
    out[4*n+2] = pw; out[4*n+3] = ph;

    float x0 = px - 0.5f * (pw - 1.0f);
    float y0 = py - 0.5f * (ph - 1.0f);
    float x1 = pw + x0 - 1.0f;
    float y1 = ph + y0 - 1.0f;
    x0 = fminf(fmaxf(x0, 0.0f), IMGW - 1.0f);
    x1 = fminf(fmaxf(x1, 0.0f), IMGW - 1.0f);
    y0 = fminf(fmaxf(y0, 0.0f), IMGH - 1.0f);
    y1 = fminf(fmaxf(y1, 0.0f), IMGH - 1.0f);
    float wsv = x1 - x0 + 1.0f;
    float hsv = y1 - y0 + 1.0f;

    float ax0 = ax - 0.5f * (aw - 1.0f);
    float ay0 = ay - 0.5f * (ah - 1.0f);
    float ax1 = aw + ax0 - 1.0f;
    float ay1 = ah + ay0 - 1.0f;
    bool anchor_valid = (ax0 >= 0.0f) && (ay0 >= 0.0f) && (ax1 < IMGW) && (ay1 < IMGH);
    bool valid = anchor_valid && (wsv >= MINSZ) && (hsv >= MINSZ);

    float score = valid ? prob : -1.0f;
    float f = -score;
    unsigned u = __float_as_uint(f);
    u = (u & 0x80000000u) ? ~u : (u | 0x80000000u);
    g_keys[n] = ((u64)u << 32) | (unsigned)n;

    g_x0[n] = x0; g_y0[n] = y0; g_x1[n] = x1; g_y1[n] = y1;
    g_ws[n] = wsv; g_hs[n] = hsv; g_prob[n] = prob;
    g_valid[n] = valid ? 1u : 0u;
}

// ---------------- 3a. rank-by-counting partials (RED to g_rank) ---------------
__global__ __launch_bounds__(288) void rank_part_kernel() {
    __shared__ u64 sk[SLICE];
    const int tid = threadIdx.x;
    const int s   = blockIdx.y;
    const int i   = blockIdx.x * 288 + tid;

    for (int j = tid; j < SLICE; j += 288) sk[j] = g_keys[s * SLICE + j];
    __syncthreads();

    const u64 key = g_keys[i];
    int cnt = 0;
    #pragma unroll 8
    for (int j = 0; j < SLICE; j++) cnt += (sk[j] < key) ? 1 : 0;
    atomicAdd(&g_rank[i], cnt);      // distinct addresses -> RED, fast
}

// ---------------- 3b. scatter boxes to sorted positions ------------------------
__global__ void scatter_rank_kernel() {
    int i = blockIdx.x * blockDim.x + threadIdx.x;
    if (i >= NN) return;
    int r = g_rank[i];
    g_order[r]  = i;
    g_bx0[r]    = g_x0[i];
    g_by0[r]    = g_y0[i];
    g_bx1[r]    = g_x1[i];
    g_by1[r]    = g_y1[i];
    g_barea[r]  = g_ws[i] * g_hs[i];
    g_bvalid[r] = g_valid[i];
}

// ---------------- 4. suppression bitmask matrix (upper triangle only) ----------
__global__ void mask_kernel() {
    const int rb = blockIdx.y, cb = blockIdx.x;
    if (cb < rb) return;                 // lower triangle never read
    const int t  = threadIdx.x;          // 64 threads
    const int i  = rb * 64 + t;

    __shared__ float cx0[64], cy0[64], cx1[64], cy1[64], car[64];
    {
        int j = cb * 64 + t;
        cx0[t] = g_bx0[j]; cy0[t] = g_by0[j];
        cx1[t] = g_bx1[j]; cy1[t] = g_by1[j];
        car[t] = g_barea[j];
    }
    __syncthreads();

    u64 w = 0ull;
    if (g_bvalid[i]) {
        float x0 = g_bx0[i], y0 = g_by0[i], x1 = g_bx1[i], y1 = g_by1[i];
        float ar = g_barea[i];
        int jbase = cb * 64;
        #pragma unroll 8
        for (int b = 0; b < 64; b++) {
            int j = jbase + b;
            if (j > i) {
                float iw = fminf(x1, cx1[b]) - fmaxf(x0, cx0[b]) + 1.0f;
                float ih = fminf(y1, cy1[b]) - fmaxf(y0, cy0[b]) + 1.0f;
                iw = fmaxf(iw, 0.0f);
                ih = fmaxf(ih, 0.0f);
                float inter = iw * ih;
                float iou = inter / (ar + car[b] - inter);
                if (iou > NMS_T) w |= (1ull << b);
            }
        }
    }
    g_mask[(size_t)i * NWORD + cb] = w;
}

// ---------------- 5. greedy NMS reduce (128-row chunks) + fused finalize -------
#define RT 1024
#define TPW 8    // threads per remv word in the update phase
__global__ __launch_bounds__(RT) void nms_reduce_kernel(
        const int* __restrict__ labels, float* __restrict__ out) {
    extern __shared__ u64 sdiag[];       // NN*2 words: per-row 128-bit diag block
    __shared__ u64 remv[NWORD];
    __shared__ u64 vword[NWORD];
    __shared__ u64 part[NWORD * TPW];
    __shared__ u64 sh_k0, sh_k1;
    __shared__ int kb[128];
    __shared__ int kcnt;
    __shared__ unsigned vhalf[NWORD * 2];

    const int tid  = threadIdx.x;
    const int lane = tid & 31;

    // preload diagonal 128x128 blocks (2 words per row)
    for (int i = tid; i < NN; i += RT) {
        int t = i >> 7;
        if (t < 40) {
            sdiag[2*i]   = g_mask[(size_t)i * NWORD + 2*t];
            sdiag[2*i+1] = g_mask[(size_t)i * NWORD + 2*t+1];
        } else {
            sdiag[2*i]   = g_mask[(size_t)i * NWORD + 80];
            sdiag[2*i+1] = 0ull;
        }
    }
    for (int w = tid; w < NWORD; w += RT) remv[w] = 0ull;
    for (int i = tid; i < NN; i += RT) {
        unsigned bal = __ballot_sync(0xFFFFFFFFu, g_bvalid[i] != 0u);
        if (lane == 0) vhalf[i >> 5] = bal;
    }
    __syncthreads();
    for (int w = tid; w < NWORD; w += RT)
        vword[w] = ((u64)vhalf[2*w+1] << 32) | (u64)vhalf[2*w];
    __syncthreads();

    for (int t = 0; t < NCH; t++) {
        const int bR = t * 128;                 // first global row of chunk
        const bool full = (t < 40);

        if (tid == 0) {
            u64 avail0 = vword[2*t] & ~remv[2*t];
            u64 avail1 = full ? (vword[2*t+1] & ~remv[2*t+1]) : 0ull;
            u64 k0 = 0ull, k1 = 0ull;
            int n = 0;
            while (avail0 | avail1) {
                int b;
                if (avail0) {
                    b = __ffsll((long long)avail0) - 1;
                    k0 |= (1ull << b);
                    avail0 &= ~(1ull << b);
                } else {
                    int bb = __ffsll((long long)avail1) - 1;
                    b = 64 + bb;
                    k1 |= (1ull << bb);
                    avail1 &= ~(1ull << bb);
                }
                kb[n++] = b;
                const u64* dd = &sdiag[(size_t)(bR + b) * 2];
                avail0 &= ~dd[0];
                avail1 &= ~dd[1];
            }
            sh_k0 = k0; sh_k1 = k1; kcnt = n;
        }
        __syncthreads();

        const int n = kcnt;
        const int w0 = 2*t + 2;
        const int nw = NWORD - w0;              // words to update (<=0 for t=40)

        // partial ORs: TPW threads per word, one parallel load round
        if (nw > 0 && n > 0) {
            int wi  = tid / TPW;
            int sub = tid % TPW;
            if (wi < nw) {
                int w = w0 + wi;
                u64 acc = 0ull;
                for (int q = sub; q < n; q += TPW)
                    acc |= g_mask[(size_t)(bR + kb[q]) * NWORD + w];
                part[wi * TPW + sub] = acc;
            }
        }
        // write keep bits for this chunk (reuse threads while loads fly)
        if (tid < 128) {
            int row = bR + tid;
            if (row < NN) {
                u64 kw = (tid < 64) ? sh_k0 : sh_k1;
                int  b = tid & 63;
                // stash keep flag in g_rank (repurposed; rank no longer needed)
                g_order[row] = g_order[row];    // no-op keep ordering
                vhalf[0] = vhalf[0];            // no-op
                ((unsigned*)&g_valid[0])[0] = g_valid[0]; // no-op
                g_bvalid[row] = (unsigned)((kw >> b) & 1ull) | (g_bvalid[row] << 1);
            }
        }
        __syncthreads();

        if (nw > 0 && n > 0 && tid < nw) {
            u64 acc = part[tid * TPW]     | part[tid * TPW + 1]
                    | part[tid * TPW + 2] | part[tid * TPW + 3]
                    | part[tid * TPW + 4] | part[tid * TPW + 5]
                    | part[tid * TPW + 6] | part[tid * TPW + 7];
            remv[w0 + tid] |= acc;
        }
        __syncthreads();
    }

    // fused finalize: g_bvalid[row] bit0 now holds keep flag (sorted order)
    for (int i = tid; i < NN; i += RT) {
        int nidx = g_order[i];
        unsigned kp = g_bvalid[i] & 1u;
        float kf = kp ? 1.0f : 0.0f;
        float x0 = g_x0[nidx], y0 = g_y0[nidx];
        float wsv = g_ws[nidx], hsv = g_hs[nidx];
        out[6*NN + 4*nidx]     = (x0 + 0.5f * (wsv - 1.0f)) * kf;
        out[6*NN + 4*nidx + 1] = (y0 + 0.5f * (hsv - 1.0f)) * kf;
        out[6*NN + 4*nidx + 2] = wsv * kf;
        out[6*NN + 4*nidx + 3] = hsv * kf;
        out[10*NN + nidx] = g_prob[nidx] * kf;
        out[11*NN + nidx] = kp ? (float)labels[nidx] : 0.0f;
        out[12*NN + nidx] = kf;
    }
}

// -------------------------------------------------------------------------------
extern "C" void kernel_launch(void* const* d_in, const int* in_sizes, int n_in,
                              void* d_out, int out_size) {
    const float* x       = (const float*)d_in[0];
    const int*   labels  = (const int*)  d_in[1];
    const float* Wrpn    = (const float*)d_in[2];
    const float* brpn    = (const float*)d_in[3];
    const float* Wc      = (const float*)d_in[4];
    const float* bc      = (const float*)d_in[5];
    const float* Wr      = (const float*)d_in[6];
    const float* br      = (const float*)d_in[7];
    const float* anchors = (const float*)d_in[8];
    float* out = (float*)d_out;

    const int nms_smem = NN * 2 * (int)sizeof(u64);   // 82944 B
    cudaFuncSetAttribute(nms_reduce_kernel,
                         cudaFuncAttributeMaxDynamicSharedMemorySize, nms_smem);

    conv_part_kernel<<<dim3(FEAT, KCHUNKS), 576>>>(x, Wrpn);
    decode_kernel<<<NPIX / 32, 288>>>(Wc, bc, Wr, br, brpn, anchors, out);
    rank_part_kernel<<<dim3(18, NSLICE), 288>>>();
    scatter_rank_kernel<<<41, 128>>>();
    mask_kernel<<<dim3(NWORD, NWORD), 64>>>();
    nms_reduce_kernel<<<1, RT, nms_smem>>>(labels, out);
}